// round 8
// baseline (speedup 1.0000x reference)
#include <cuda_runtime.h>
#include <cuda_bf16.h>
#include <cuda_fp8.h>
#include <cstdint>

// Problem constants
#define HH 96
#define WW 96
#define NPIX 9216          // 96*96
#define OHW 94
#define QN 8836            // 94*94 patches on each side
#define CCH 256            // channels = GEMM K (fp8)
#define CU 128             // K in packed fp8x2 units (uint16)
#define MTIL 72            // 9216 / 128

// Static device scratch (no runtime allocation)
__device__ uint16_t g_Xt[(size_t)NPIX * CU];           // inp [pix][unit], e4m3 x2
__device__ uint16_t g_Yt[(size_t)NPIX * CU];           // tgt [pix][unit], e4m3 x2
__device__ __nv_bfloat16 g_Pb[(size_t)NPIX * NPIX + 256]; // pixel Gram matrix, bf16 (+tap pad)
__device__ float g_invY[NPIX];                         // 1/style_norm by y (0 if invalid)
__device__ int   g_nn[QN];
__device__ float g_loss[QN];

__device__ __forceinline__ uint16_t f2_to_e4m3x2(float lo, float hi) {
    uint16_t r;
    asm("cvt.rn.satfinite.e4m3x2.f32 %0, %1, %2;" : "=h"(r) : "f"(hi), "f"(lo));
    return r;
}
__device__ __forceinline__ float2 e4m3x2_to_f2(uint16_t v) {
    uint32_t h2;
    asm("cvt.rn.f16x2.e4m3x2 %0, %1;" : "=r"(h2) : "h"(v));
    __half2 hh = *reinterpret_cast<__half2*>(&h2);
    return make_float2(__low2float(hh), __high2float(hh));
}

// ---------------------------------------------------------------------------
// K0: transpose+convert images: [256][9216] fp32 -> [9216][128] e4m3x2 units
// (unit u packs channels 2u, 2u+1; order consistent across X and Y)
// ---------------------------------------------------------------------------
__global__ void transpose_kernel(const float* __restrict__ inp, const float* __restrict__ tgt) {
    __shared__ float t[32][33];
    const float* src = blockIdx.z ? tgt : inp;
    uint16_t* dst = blockIdx.z ? g_Yt : g_Xt;
    int p0 = blockIdx.x * 32, c0 = blockIdx.y * 32;
    int tx = threadIdx.x & 31, ty = threadIdx.x >> 5;  // 32 x 8
#pragma unroll
    for (int r = 0; r < 4; ++r) {
        int c = c0 + ty + r * 8;
        t[ty + r * 8][tx] = src[(size_t)c * NPIX + p0 + tx];
    }
    __syncthreads();
#pragma unroll
    for (int r = 0; r < 2; ++r) {
        int k = ty + r * 8;                 // unit within tile: 0..15
        int p = p0 + tx;
        dst[(size_t)p * CU + (c0 >> 1) + k] = f2_to_e4m3x2(t[2 * k][tx], t[2 * k + 1][tx]);
    }
}

// ---------------------------------------------------------------------------
// K0b: style patch inverse norms from QUANTIZED Y (consistent with resp).
// g_invY[y] for y = u*96+v, u,v < 94; 0 elsewhere (zero-init, never written).
// 128 threads: one unit each, 9 pixel rows.
// ---------------------------------------------------------------------------
__global__ void invnorm_kernel() {
    int q = blockIdx.x;            // 0..QN-1
    int tid = threadIdx.x;         // 128 = one unit each
    int u = q / OHW, v = q % OHW;
    int y = u * WW + v;
    float ss = 0.f;
#pragma unroll
    for (int t = 0; t < 9; ++t) {
        int pix = y + (t / 3) * WW + (t % 3);
        float2 f = e4m3x2_to_f2(g_Yt[(size_t)pix * CU + tid]);
        ss += f.x * f.x + f.y * f.y;
    }
    __shared__ float red[128];
    red[tid] = ss;
    __syncthreads();
    for (int s = 64; s > 0; s >>= 1) {
        if (tid < s) red[tid] += red[tid + s];
        __syncthreads();
    }
    if (tid == 0) g_invY[y] = 1.0f / sqrtf(red[0]);
}

// ---------------------------------------------------------------------------
// K1: P = Xt * Yt^T  (9216x9216, K=256 fp8 -> bf16). 128x128 tile, k-chunk of
// 32 units (64 fp8), double-buffered cp.async, 8 warps. Identical structure to
// the validated bf16 pipeline ("unit" = 2 bytes); mma is m16n8k32 e4m3.
// ---------------------------------------------------------------------------
__device__ __forceinline__ void cpa16(void* s, const void* g) {
    uint32_t sa = (uint32_t)__cvta_generic_to_shared(s);
    asm volatile("cp.async.cg.shared.global [%0], [%1], 16;" :: "r"(sa), "l"(g));
}
__device__ __forceinline__ void ldsm4(uint32_t* r, const uint16_t* p) {
    uint32_t sa = (uint32_t)__cvta_generic_to_shared(p);
    asm volatile("ldmatrix.sync.aligned.m8n8.x4.shared.b16 {%0,%1,%2,%3}, [%4];"
                 : "=r"(r[0]), "=r"(r[1]), "=r"(r[2]), "=r"(r[3]) : "r"(sa));
}
__device__ __forceinline__ void ldsm2(uint32_t* r, const uint16_t* p) {
    uint32_t sa = (uint32_t)__cvta_generic_to_shared(p);
    asm volatile("ldmatrix.sync.aligned.m8n8.x2.shared.b16 {%0,%1}, [%2];"
                 : "=r"(r[0]), "=r"(r[1]) : "r"(sa));
}
__device__ __forceinline__ void mma16832f8(float* c, const uint32_t* a, const uint32_t* b) {
    asm volatile(
        "mma.sync.aligned.m16n8k32.row.col.f32.e4m3.e4m3.f32 "
        "{%0,%1,%2,%3}, {%4,%5,%6,%7}, {%8,%9}, {%0,%1,%2,%3};"
        : "+f"(c[0]), "+f"(c[1]), "+f"(c[2]), "+f"(c[3])
        : "r"(a[0]), "r"(a[1]), "r"(a[2]), "r"(a[3]), "r"(b[0]), "r"(b[1]));
}

__global__ __launch_bounds__(256) void gemm_kernel() {
    __shared__ __align__(16) uint16_t sA[2][128 * 40];
    __shared__ __align__(16) uint16_t sB[2][128 * 40];
    const int mt = blockIdx.y, nt = blockIdx.x;
    const int tid = threadIdx.x;
    const int lane = tid & 31, warp = tid >> 5;
    const int wm = warp >> 1, wn = warp & 1;

    float acc[2][8][4];
#pragma unroll
    for (int a = 0; a < 2; a++)
#pragma unroll
        for (int b = 0; b < 8; b++)
#pragma unroll
            for (int c = 0; c < 4; c++) acc[a][b][c] = 0.f;

    auto load_tiles = [&](int buf, int k0) {   // k0 in units
#pragma unroll
        for (int u = 0; u < 2; ++u) {
            int ch = tid + u * 256;
            int row = ch >> 2, c4 = ch & 3;
            cpa16(&sA[buf][row * 40 + c4 * 8],
                  g_Xt + (size_t)(mt * 128 + row) * CU + k0 + c4 * 8);
            cpa16(&sB[buf][row * 40 + c4 * 8],
                  g_Yt + (size_t)(nt * 128 + row) * CU + k0 + c4 * 8);
        }
        asm volatile("cp.async.commit_group;");
    };

    load_tiles(0, 0);
    const int NKI = CU / 32;   // 4
    for (int kk = 0; kk < NKI; ++kk) {
        int buf = kk & 1;
        if (kk + 1 < NKI) {
            load_tiles(buf ^ 1, (kk + 1) * 32);
            asm volatile("cp.async.wait_group 1;");
        } else {
            asm volatile("cp.async.wait_group 0;");
        }
        __syncthreads();
#pragma unroll
        for (int ks = 0; ks < 2; ++ks) {
            uint32_t afr[2][4];
#pragma unroll
            for (int mi = 0; mi < 2; ++mi) {
                int r = wm * 32 + mi * 16 + (lane & 7) + ((lane >> 3) & 1) * 8;
                int cch = ks * 2 + (lane >> 4);
                ldsm4(afr[mi], &sA[buf][r * 40 + cch * 8]);
            }
            uint32_t bfr[8][2];
#pragma unroll
            for (int ni = 0; ni < 8; ++ni) {
                int l = lane & 15;
                int r = wn * 64 + ni * 8 + (l & 7);
                int cch = ks * 2 + ((l >> 3) & 1);
                ldsm2(bfr[ni], &sB[buf][r * 40 + cch * 8]);
            }
#pragma unroll
            for (int mi = 0; mi < 2; ++mi)
#pragma unroll
                for (int ni = 0; ni < 8; ++ni)
                    mma16832f8(acc[mi][ni], afr[mi], bfr[ni]);
        }
        __syncthreads();
    }

    // Epilogue: convert to bf16 pairs and stream to g_Pb (coalesced 4B/lane)
#pragma unroll
    for (int mi = 0; mi < 2; ++mi) {
#pragma unroll
        for (int ni = 0; ni < 8; ++ni) {
            int r0 = mt * 128 + wm * 32 + mi * 16 + (lane >> 2);
            int c0 = nt * 128 + wn * 64 + ni * 8 + (lane & 3) * 2;
            __nv_bfloat162 v01 = __floats2bfloat162_rn(acc[mi][ni][0], acc[mi][ni][1]);
            __nv_bfloat162 v23 = __floats2bfloat162_rn(acc[mi][ni][2], acc[mi][ni][3]);
            *reinterpret_cast<__nv_bfloat162*>(&g_Pb[(size_t)r0 * NPIX + c0]) = v01;
            *reinterpret_cast<__nv_bfloat162*>(&g_Pb[(size_t)(r0 + 8) * NPIX + c0]) = v23;
        }
    }
}

// ---------------------------------------------------------------------------
// K2: fused 9-tap diagonal sum + invnorm scale + argmax on bf16 P.
// Taps grouped by column offset o = t%3, accumulated packed bf16x2; one
// realignment per group per iteration. (unchanged from round 5)
// ---------------------------------------------------------------------------
__device__ __forceinline__ uint32_t badd2(uint32_t a, uint32_t b) {
    __nv_bfloat162 av, bv;
    *reinterpret_cast<uint32_t*>(&av) = a;
    *reinterpret_cast<uint32_t*>(&bv) = b;
    __nv_bfloat162 rv = __hadd2(av, bv);
    return *reinterpret_cast<uint32_t*>(&rv);
}

__global__ __launch_bounds__(256) void argmax_kernel() {
    int w = threadIdx.x >> 5, lane = threadIdx.x & 31;
    int qid = blockIdx.x * 8 + w;
    if (qid >= QN) return;
    int i = qid / OHW, j = qid % OHW;
    int x = i * WW + j;

    const __nv_bfloat16* tp[9];
#pragma unroll
    for (int t = 0; t < 9; ++t) {
        int dl = (t / 3) * WW + (t % 3);
        tp[t] = g_Pb + (size_t)(x + dl) * NPIX + (dl - (t % 3));
    }

    float best = -3.0e38f;
    int bestY = 0;

#pragma unroll 1
    for (int g = 0; g < NPIX / 256; ++g) {   // 36 iterations
        const int off = g * 256 + lane * 8;
        const int ybase = off;

        uint4 A0 = {0u, 0u, 0u, 0u}, A1 = A0, A2 = A0;
        uint32_t nA1 = 0u, nA2 = 0u;

#pragma unroll
        for (int t = 0; t < 9; ++t) {
            uint4 ch = __ldg(reinterpret_cast<const uint4*>(tp[t] + off));
            const int o = t % 3;
            if (o == 0) {
                A0.x = badd2(A0.x, ch.x); A0.y = badd2(A0.y, ch.y);
                A0.z = badd2(A0.z, ch.z); A0.w = badd2(A0.w, ch.w);
            } else if (o == 1) {
                A1.x = badd2(A1.x, ch.x); A1.y = badd2(A1.y, ch.y);
                A1.z = badd2(A1.z, ch.z); A1.w = badd2(A1.w, ch.w);
                if (lane == 31)
                    nA1 = badd2(nA1, __ldg(reinterpret_cast<const uint32_t*>(tp[t] + off + 8)));
            } else {
                A2.x = badd2(A2.x, ch.x); A2.y = badd2(A2.y, ch.y);
                A2.z = badd2(A2.z, ch.z); A2.w = badd2(A2.w, ch.w);
                if (lane == 31)
                    nA2 = badd2(nA2, __ldg(reinterpret_cast<const uint32_t*>(tp[t] + off + 8)));
            }
        }

        uint32_t n1 = __shfl_down_sync(0xFFFFFFFFu, A1.x, 1);
        uint32_t n2 = __shfl_down_sync(0xFFFFFFFFu, A2.x, 1);
        if (lane == 31) { n1 = nA1; n2 = nA2; }

        uint32_t b1[4], b2[4];
        b1[0] = __byte_perm(A1.x, A1.y, 0x5432);
        b1[1] = __byte_perm(A1.y, A1.z, 0x5432);
        b1[2] = __byte_perm(A1.z, A1.w, 0x5432);
        b1[3] = __byte_perm(A1.w, n1,   0x5432);
        b2[0] = A2.y; b2[1] = A2.z; b2[2] = A2.w; b2[3] = n2;

        float4 i0 = __ldg(reinterpret_cast<const float4*>(&g_invY[ybase]));
        float4 i1 = __ldg(reinterpret_cast<const float4*>(&g_invY[ybase + 4]));
        const float iv[8] = {i0.x, i0.y, i0.z, i0.w, i1.x, i1.y, i1.z, i1.w};
        const uint32_t a0w[4] = {A0.x, A0.y, A0.z, A0.w};
#pragma unroll
        for (int wi = 0; wi < 4; ++wi) {
            float lo = __uint_as_float(a0w[wi] << 16) +
                       __uint_as_float(b1[wi] << 16) +
                       __uint_as_float(b2[wi] << 16);
            float hi = __uint_as_float(a0w[wi] & 0xFFFF0000u) +
                       __uint_as_float(b1[wi] & 0xFFFF0000u) +
                       __uint_as_float(b2[wi] & 0xFFFF0000u);
            float r0 = lo * iv[wi * 2];
            float r1 = hi * iv[wi * 2 + 1];
            if (r0 > best) { best = r0; bestY = ybase + wi * 2; }
            if (r1 > best) { best = r1; bestY = ybase + wi * 2 + 1; }
        }
    }

#pragma unroll
    for (int offw = 16; offw; offw >>= 1) {
        float ob = __shfl_xor_sync(0xFFFFFFFFu, best, offw);
        int oy = __shfl_xor_sync(0xFFFFFFFFu, bestY, offw);
        if (ob > best || (ob == best && oy < bestY)) { best = ob; bestY = oy; }
    }
    if (lane == 0)
        g_nn[qid] = (bestY / WW) * OHW + (bestY % WW);
}

// ---------------------------------------------------------------------------
// K3: exact fp32 gathered MSE from the raw images (quantization only ever
// touched the argmax, not the loss value).
// ---------------------------------------------------------------------------
__global__ void loss_kernel(const float* __restrict__ inp, const float* __restrict__ tgt) {
    int q = blockIdx.x;       // < QN
    int tid = threadIdx.x;    // 256
    int snn = g_nn[q];
    int i = q / OHW, j = q % OHW;
    int u = snn / OHW, v = snn % OHW;
    float sum = 0.f;
#pragma unroll
    for (int it = 0; it < 9; ++it) {
        int d = it * 256 + tid;
        int c = d / 9, t = d - c * 9;
        int oa = c * (HH * WW) + (i + t / 3) * WW + (j + t % 3);
        int ob = c * (HH * WW) + (u + t / 3) * WW + (v + t % 3);
        float df = inp[oa] - tgt[ob];
        sum += df * df;
    }
    __shared__ float red[256];
    red[tid] = sum;
    __syncthreads();
    for (int s = 128; s > 0; s >>= 1) {
        if (tid < s) red[tid] += red[tid + s];
        __syncthreads();
    }
    if (tid == 0) g_loss[q] = red[0];
}

// K4: deterministic scalar reduce -> loss = sum / (QN * 2304)
__global__ void final_kernel(float* __restrict__ out) {
    __shared__ float red[1024];
    int tid = threadIdx.x;
    float acc = 0.f;
    for (int i = tid; i < QN; i += 1024) acc += g_loss[i];
    red[tid] = acc;
    __syncthreads();
    for (int s = 512; s > 0; s >>= 1) {
        if (tid < s) red[tid] += red[tid + s];
        __syncthreads();
    }
    if (tid == 0) out[0] = red[0] / ((float)QN * 2304.0f);
}

extern "C" void kernel_launch(void* const* d_in, const int* in_sizes, int n_in,
                              void* d_out, int out_size) {
    const float* inp = (const float*)d_in[0];   // input
    const float* tgt = (const float*)d_in[1];   // target
    float* out = (float*)d_out;

    dim3 tg(NPIX / 32, CCH / 32, 2);
    transpose_kernel<<<tg, 256>>>(inp, tgt);
    invnorm_kernel<<<QN, 128>>>();
    dim3 gg(MTIL, MTIL);
    gemm_kernel<<<gg, 256>>>();
    argmax_kernel<<<(QN + 7) / 8, 256>>>();
    loss_kernel<<<QN, 256>>>(inp, tgt);
    final_kernel<<<1, 1024>>>(out);
}

// round 9
// speedup vs baseline: 1.5620x; 1.5620x over previous
#include <cuda_runtime.h>
#include <cuda_bf16.h>
#include <cstdint>

// Problem constants
#define HH 96
#define WW 96
#define NPIX 9216          // 96*96
#define OHW 94
#define QN 8836            // 94*94 patches on each side
#define CCH 256            // channels = GEMM K
#define MTIL 72            // 9216 / 128

// Static device scratch (no runtime allocation)
__device__ __nv_bfloat16 g_Xt[(size_t)NPIX * CCH];     // inp transposed  [pix][c] bf16
__device__ __nv_bfloat16 g_Yt[(size_t)NPIX * CCH];     // tgt transposed  [pix][c] bf16
__device__ __nv_bfloat16 g_Pb[(size_t)NPIX * NPIX + 256]; // pixel Gram matrix, bf16 (+tap pad)
__device__ float g_invY[NPIX];                         // 1/style_norm by y (0 if invalid)
__device__ int   g_nn[QN];
__device__ float g_loss[QN];

// ---------------------------------------------------------------------------
// K0: transpose+convert images: [256][9216] fp32 -> [9216][256] bf16
// ---------------------------------------------------------------------------
__global__ void transpose_kernel(const float* __restrict__ inp, const float* __restrict__ tgt) {
    __shared__ float t[32][33];
    const float* src = blockIdx.z ? tgt : inp;
    __nv_bfloat16* dst = blockIdx.z ? g_Yt : g_Xt;
    int p0 = blockIdx.x * 32, c0 = blockIdx.y * 32;
    int tx = threadIdx.x & 31, ty = threadIdx.x >> 5;  // 32 x 8
#pragma unroll
    for (int r = 0; r < 4; ++r) {
        int c = c0 + ty + r * 8;
        t[ty + r * 8][tx] = src[(size_t)c * NPIX + p0 + tx];
    }
    __syncthreads();
#pragma unroll
    for (int r = 0; r < 4; ++r) {
        int p = p0 + ty + r * 8;
        dst[(size_t)p * CCH + c0 + tx] = __float2bfloat16(t[tx][ty + r * 8]);
    }
}

// ---------------------------------------------------------------------------
// K0b: style patch inverse norms -> g_invY[y], y = u*96+v (0 elsewhere;
// zero-init at module load, invalid slots never written)
// ---------------------------------------------------------------------------
__global__ void invnorm_kernel() {
    int q = blockIdx.x;            // 0..QN-1
    int tid = threadIdx.x;         // 256 = one channel each
    int u = q / OHW, v = q % OHW;
    int y = u * WW + v;
    float ss = 0.f;
#pragma unroll
    for (int t = 0; t < 9; ++t) {
        int pix = y + (t / 3) * WW + (t % 3);
        float val = __bfloat162float(g_Yt[(size_t)pix * CCH + tid]);
        ss += val * val;
    }
    __shared__ float red[256];
    red[tid] = ss;
    __syncthreads();
    for (int s = 128; s > 0; s >>= 1) {
        if (tid < s) red[tid] += red[tid + s];
        __syncthreads();
    }
    if (tid == 0) g_invY[y] = 1.0f / sqrtf(red[0]);
}

// ---------------------------------------------------------------------------
// K1: P = Xt * Yt^T  (9216x9216x256 bf16 -> bf16). 128x128 tile, k-chunk 32,
// double-buffered cp.async, 8 warps. (validated HMMA pipeline, round-6 exact)
// ---------------------------------------------------------------------------
__device__ __forceinline__ void cpa16(void* s, const void* g) {
    uint32_t sa = (uint32_t)__cvta_generic_to_shared(s);
    asm volatile("cp.async.cg.shared.global [%0], [%1], 16;" :: "r"(sa), "l"(g));
}
__device__ __forceinline__ void ldsm4(uint32_t* r, const __nv_bfloat16* p) {
    uint32_t sa = (uint32_t)__cvta_generic_to_shared(p);
    asm volatile("ldmatrix.sync.aligned.m8n8.x4.shared.b16 {%0,%1,%2,%3}, [%4];"
                 : "=r"(r[0]), "=r"(r[1]), "=r"(r[2]), "=r"(r[3]) : "r"(sa));
}
__device__ __forceinline__ void ldsm2(uint32_t* r, const __nv_bfloat16* p) {
    uint32_t sa = (uint32_t)__cvta_generic_to_shared(p);
    asm volatile("ldmatrix.sync.aligned.m8n8.x2.shared.b16 {%0,%1}, [%2];"
                 : "=r"(r[0]), "=r"(r[1]) : "r"(sa));
}
__device__ __forceinline__ void mma16816(float* c, const uint32_t* a, const uint32_t* b) {
    asm volatile(
        "mma.sync.aligned.m16n8k16.row.col.f32.bf16.bf16.f32 "
        "{%0,%1,%2,%3}, {%4,%5,%6,%7}, {%8,%9}, {%0,%1,%2,%3};"
        : "+f"(c[0]), "+f"(c[1]), "+f"(c[2]), "+f"(c[3])
        : "r"(a[0]), "r"(a[1]), "r"(a[2]), "r"(a[3]), "r"(b[0]), "r"(b[1]));
}

__global__ __launch_bounds__(256) void gemm_kernel() {
    __shared__ __align__(16) __nv_bfloat16 sA[2][128 * 40];
    __shared__ __align__(16) __nv_bfloat16 sB[2][128 * 40];
    const int mt = blockIdx.y, nt = blockIdx.x;
    const int tid = threadIdx.x;
    const int lane = tid & 31, warp = tid >> 5;
    const int wm = warp >> 1, wn = warp & 1;

    float acc[2][8][4];
#pragma unroll
    for (int a = 0; a < 2; a++)
#pragma unroll
        for (int b = 0; b < 8; b++)
#pragma unroll
            for (int c = 0; c < 4; c++) acc[a][b][c] = 0.f;

    auto load_tiles = [&](int buf, int k0) {
#pragma unroll
        for (int u = 0; u < 2; ++u) {
            int ch = tid + u * 256;
            int row = ch >> 2, c4 = ch & 3;
            cpa16(&sA[buf][row * 40 + c4 * 8],
                  g_Xt + (size_t)(mt * 128 + row) * CCH + k0 + c4 * 8);
            cpa16(&sB[buf][row * 40 + c4 * 8],
                  g_Yt + (size_t)(nt * 128 + row) * CCH + k0 + c4 * 8);
        }
        asm volatile("cp.async.commit_group;");
    };

    load_tiles(0, 0);
    const int NKI = CCH / 32;  // 8
    for (int kk = 0; kk < NKI; ++kk) {
        int buf = kk & 1;
        if (kk + 1 < NKI) {
            load_tiles(buf ^ 1, (kk + 1) * 32);
            asm volatile("cp.async.wait_group 1;");
        } else {
            asm volatile("cp.async.wait_group 0;");
        }
        __syncthreads();
#pragma unroll
        for (int ks = 0; ks < 2; ++ks) {
            uint32_t afr[2][4];
#pragma unroll
            for (int mi = 0; mi < 2; ++mi) {
                int r = wm * 32 + mi * 16 + (lane & 7) + ((lane >> 3) & 1) * 8;
                int cch = ks * 2 + (lane >> 4);
                ldsm4(afr[mi], &sA[buf][r * 40 + cch * 8]);
            }
            uint32_t bfr[8][2];
#pragma unroll
            for (int ni = 0; ni < 8; ++ni) {
                int l = lane & 15;
                int r = wn * 64 + ni * 8 + (l & 7);
                int cch = ks * 2 + ((l >> 3) & 1);
                ldsm2(bfr[ni], &sB[buf][r * 40 + cch * 8]);
            }
#pragma unroll
            for (int mi = 0; mi < 2; ++mi)
#pragma unroll
                for (int ni = 0; ni < 8; ++ni)
                    mma16816(acc[mi][ni], afr[mi], bfr[ni]);
        }
        __syncthreads();
    }

    // Epilogue: convert to bf16 pairs and stream to g_Pb (coalesced 4B/lane)
#pragma unroll
    for (int mi = 0; mi < 2; ++mi) {
#pragma unroll
        for (int ni = 0; ni < 8; ++ni) {
            int r0 = mt * 128 + wm * 32 + mi * 16 + (lane >> 2);
            int c0 = nt * 128 + wn * 64 + ni * 8 + (lane & 3) * 2;
            __nv_bfloat162 v01 = __floats2bfloat162_rn(acc[mi][ni][0], acc[mi][ni][1]);
            __nv_bfloat162 v23 = __floats2bfloat162_rn(acc[mi][ni][2], acc[mi][ni][3]);
            *reinterpret_cast<__nv_bfloat162*>(&g_Pb[(size_t)r0 * NPIX + c0]) = v01;
            *reinterpret_cast<__nv_bfloat162*>(&g_Pb[(size_t)(r0 + 8) * NPIX + c0]) = v23;
        }
    }
}

// ---------------------------------------------------------------------------
// K2: fused 9-tap diagonal sum + invnorm scale + argmax on bf16 P.
// Taps grouped by column offset o = t%3, accumulated packed bf16x2; one
// realignment per group per iteration. This round:
//  - single base pointer + compile-time tap offsets (LDG immediates, -18 regs)
//  - FMAX-tree + deferred index scan (replaces 16 predicated updates/iter)
// ---------------------------------------------------------------------------
__device__ __forceinline__ uint32_t badd2(uint32_t a, uint32_t b) {
    __nv_bfloat162 av, bv;
    *reinterpret_cast<uint32_t*>(&av) = a;
    *reinterpret_cast<uint32_t*>(&bv) = b;
    __nv_bfloat162 rv = __hadd2(av, bv);
    return *reinterpret_cast<uint32_t*>(&rv);
}

// Tap element offsets from (row x, aligned col 0): dl*NPIX + (dl - o), dl = (t/3)*96 + t%3
#define TAPOFF(t) (((t) / 3 * WW + (t) % 3) * NPIX + ((t) / 3 * WW))

__global__ __launch_bounds__(256) void argmax_kernel() {
    int w = threadIdx.x >> 5, lane = threadIdx.x & 31;
    int qid = blockIdx.x * 8 + w;
    if (qid >= QN) return;
    int i = qid / OHW, j = qid % OHW;
    const __nv_bfloat16* base = g_Pb + (size_t)(i * WW + j) * NPIX;

    float best = -3.0e38f;
    int bestY = 0;

#pragma unroll 1
    for (int g = 0; g < NPIX / 256; ++g) {   // 36 iterations
        const int off = g * 256 + lane * 8;
        const int ybase = off;
        const __nv_bfloat16* p = base + off;

        uint4 A0 = {0u, 0u, 0u, 0u}, A1 = A0, A2 = A0;
        uint32_t nA1 = 0u, nA2 = 0u;

#pragma unroll
        for (int t = 0; t < 9; ++t) {
            uint4 ch = __ldg(reinterpret_cast<const uint4*>(p + TAPOFF(t)));
            const int o = t % 3;
            if (o == 0) {
                A0.x = badd2(A0.x, ch.x); A0.y = badd2(A0.y, ch.y);
                A0.z = badd2(A0.z, ch.z); A0.w = badd2(A0.w, ch.w);
            } else if (o == 1) {
                A1.x = badd2(A1.x, ch.x); A1.y = badd2(A1.y, ch.y);
                A1.z = badd2(A1.z, ch.z); A1.w = badd2(A1.w, ch.w);
                if (lane == 31)
                    nA1 = badd2(nA1, __ldg(reinterpret_cast<const uint32_t*>(p + TAPOFF(t) + 8)));
            } else {
                A2.x = badd2(A2.x, ch.x); A2.y = badd2(A2.y, ch.y);
                A2.z = badd2(A2.z, ch.z); A2.w = badd2(A2.w, ch.w);
                if (lane == 31)
                    nA2 = badd2(nA2, __ldg(reinterpret_cast<const uint32_t*>(p + TAPOFF(t) + 8)));
            }
        }

        // Boundary words: next lane's first packed word (covers elements 8,9).
        uint32_t n1 = __shfl_down_sync(0xFFFFFFFFu, A1.x, 1);
        uint32_t n2 = __shfl_down_sync(0xFFFFFFFFu, A2.x, 1);
        if (lane == 31) { n1 = nA1; n2 = nA2; }

        // Realign group1 by 1 element (2 bytes), group2 by 2 elements (1 word).
        uint32_t b1[4], b2[4];
        b1[0] = __byte_perm(A1.x, A1.y, 0x5432);
        b1[1] = __byte_perm(A1.y, A1.z, 0x5432);
        b1[2] = __byte_perm(A1.z, A1.w, 0x5432);
        b1[3] = __byte_perm(A1.w, n1,   0x5432);
        b2[0] = A2.y; b2[1] = A2.z; b2[2] = A2.w; b2[3] = n2;

        // Combine groups in fp32, scale by invnorm.
        float4 i0 = __ldg(reinterpret_cast<const float4*>(&g_invY[ybase]));
        float4 i1 = __ldg(reinterpret_cast<const float4*>(&g_invY[ybase + 4]));
        const float iv[8] = {i0.x, i0.y, i0.z, i0.w, i1.x, i1.y, i1.z, i1.w};
        const uint32_t a0w[4] = {A0.x, A0.y, A0.z, A0.w};
        float r[8];
#pragma unroll
        for (int wi = 0; wi < 4; ++wi) {
            float lo = __uint_as_float(a0w[wi] << 16) +
                       __uint_as_float(b1[wi] << 16) +
                       __uint_as_float(b2[wi] << 16);
            float hi = __uint_as_float(a0w[wi] & 0xFFFF0000u) +
                       __uint_as_float(b1[wi] & 0xFFFF0000u) +
                       __uint_as_float(b2[wi] & 0xFFFF0000u);
            r[wi * 2]     = lo * iv[wi * 2];
            r[wi * 2 + 1] = hi * iv[wi * 2 + 1];
        }

        // FMAX tree; index scan only on improvement (strict > keeps earlier
        // (smaller-y) winners on ties; descending scan -> smallest e wins).
        float m01 = fmaxf(r[0], r[1]), m23 = fmaxf(r[2], r[3]);
        float m45 = fmaxf(r[4], r[5]), m67 = fmaxf(r[6], r[7]);
        float m = fmaxf(fmaxf(m01, m23), fmaxf(m45, m67));
        if (m > best) {
            best = m;
#pragma unroll
            for (int e = 7; e >= 0; --e)
                if (r[e] == m) bestY = ybase + e;
        }
    }

    // Warp reduce: largest resp, tie -> smallest y (matches jnp.argmax).
#pragma unroll
    for (int offw = 16; offw; offw >>= 1) {
        float ob = __shfl_xor_sync(0xFFFFFFFFu, best, offw);
        int oy = __shfl_xor_sync(0xFFFFFFFFu, bestY, offw);
        if (ob > best || (ob == best && oy < bestY)) { best = ob; bestY = oy; }
    }
    if (lane == 0)
        g_nn[qid] = (bestY / WW) * OHW + (bestY % WW);
}

// ---------------------------------------------------------------------------
// K3: exact fp32 gathered MSE from the raw images (GEMM/bf16 precision only
// ever touched the argmax, not the loss value).
// ---------------------------------------------------------------------------
__global__ void loss_kernel(const float* __restrict__ inp, const float* __restrict__ tgt) {
    int q = blockIdx.x;       // < QN
    int tid = threadIdx.x;    // 256
    int snn = g_nn[q];
    int i = q / OHW, j = q % OHW;
    int u = snn / OHW, v = snn % OHW;
    float sum = 0.f;
#pragma unroll
    for (int it = 0; it < 9; ++it) {
        int d = it * 256 + tid;
        int c = d / 9, t = d - c * 9;
        int oa = c * (HH * WW) + (i + t / 3) * WW + (j + t % 3);
        int ob = c * (HH * WW) + (u + t / 3) * WW + (v + t % 3);
        float df = inp[oa] - tgt[ob];
        sum += df * df;
    }
    __shared__ float red[256];
    red[tid] = sum;
    __syncthreads();
    for (int s = 128; s > 0; s >>= 1) {
        if (tid < s) red[tid] += red[tid + s];
        __syncthreads();
    }
    if (tid == 0) g_loss[q] = red[0];
}

// K4: deterministic scalar reduce -> loss = sum / (QN * 2304)
__global__ void final_kernel(float* __restrict__ out) {
    __shared__ float red[1024];
    int tid = threadIdx.x;
    float acc = 0.f;
    for (int i = tid; i < QN; i += 1024) acc += g_loss[i];
    red[tid] = acc;
    __syncthreads();
    for (int s = 512; s > 0; s >>= 1) {
        if (tid < s) red[tid] += red[tid + s];
        __syncthreads();
    }
    if (tid == 0) out[0] = red[0] / ((float)QN * 2304.0f);
}

extern "C" void kernel_launch(void* const* d_in, const int* in_sizes, int n_in,
                              void* d_out, int out_size) {
    const float* inp = (const float*)d_in[0];   // input
    const float* tgt = (const float*)d_in[1];   // target
    float* out = (float*)d_out;

    dim3 tg(NPIX / 32, CCH / 32, 2);
    transpose_kernel<<<tg, 256>>>(inp, tgt);
    invnorm_kernel<<<QN, 256>>>();
    dim3 gg(MTIL, MTIL);
    gemm_kernel<<<gg, 256>>>();
    argmax_kernel<<<(QN + 7) / 8, 256>>>();
    loss_kernel<<<QN, 256>>>(inp, tgt);
    final_kernel<<<1, 1024>>>(out);
}

// round 11
// speedup vs baseline: 1.6471x; 1.0545x over previous
#include <cuda_runtime.h>
#include <cuda_bf16.h>
#include <cstdint>

// Problem constants
#define HH 96
#define WW 96
#define NPIX 9216          // 96*96
#define OHW 94
#define QN 8836            // 94*94 patches on each side
#define CCH 256            // channels = GEMM K
#define MTIL 72            // 9216 / 128

// Static device scratch (no runtime allocation)
__device__ __nv_bfloat16 g_Xt[(size_t)NPIX * CCH];     // inp transposed  [pix][c] bf16
__device__ __nv_bfloat16 g_Yt[(size_t)NPIX * CCH];     // tgt transposed  [pix][c] bf16
__device__ __nv_bfloat16 g_Pb[(size_t)NPIX * NPIX + 256]; // pixel Gram matrix, bf16 (+tap pad)
__device__ float g_invY[NPIX];                         // 1/style_norm by y (0 if invalid)
__device__ int   g_nn[QN];
__device__ float g_loss[QN];

// ---------------------------------------------------------------------------
// K0: transpose+convert images: [256][9216] fp32 -> [9216][256] bf16
// ---------------------------------------------------------------------------
__global__ void transpose_kernel(const float* __restrict__ inp, const float* __restrict__ tgt) {
    __shared__ float t[32][33];
    const float* src = blockIdx.z ? tgt : inp;
    __nv_bfloat16* dst = blockIdx.z ? g_Yt : g_Xt;
    int p0 = blockIdx.x * 32, c0 = blockIdx.y * 32;
    int tx = threadIdx.x & 31, ty = threadIdx.x >> 5;  // 32 x 8
#pragma unroll
    for (int r = 0; r < 4; ++r) {
        int c = c0 + ty + r * 8;
        t[ty + r * 8][tx] = src[(size_t)c * NPIX + p0 + tx];
    }
    __syncthreads();
#pragma unroll
    for (int r = 0; r < 4; ++r) {
        int p = p0 + ty + r * 8;
        dst[(size_t)p * CCH + c0 + tx] = __float2bfloat16(t[tx][ty + r * 8]);
    }
}

// ---------------------------------------------------------------------------
// K0b: style patch inverse norms -> g_invY[y], y = u*96+v (0 elsewhere;
// zero-init at module load, invalid slots never written)
// ---------------------------------------------------------------------------
__global__ void invnorm_kernel() {
    int q = blockIdx.x;            // 0..QN-1
    int tid = threadIdx.x;         // 256 = one channel each
    int u = q / OHW, v = q % OHW;
    int y = u * WW + v;
    float ss = 0.f;
#pragma unroll
    for (int t = 0; t < 9; ++t) {
        int pix = y + (t / 3) * WW + (t % 3);
        float val = __bfloat162float(g_Yt[(size_t)pix * CCH + tid]);
        ss += val * val;
    }
    __shared__ float red[256];
    red[tid] = ss;
    __syncthreads();
    for (int s = 128; s > 0; s >>= 1) {
        if (tid < s) red[tid] += red[tid + s];
        __syncthreads();
    }
    if (tid == 0) g_invY[y] = 1.0f / sqrtf(red[0]);
}

// ---------------------------------------------------------------------------
// K1: P = Xt * Yt^T  (9216x9216x256 bf16 -> bf16). 128x128 CTA tile, k-chunk
// 32, double-buffered cp.async. THIS ROUND: 4 warps (128 thr), warp tile
// 64x64 -> 32 HMMA : 8 LDSM per k-step (was 16:10), B via ldmatrix.x4.
// ---------------------------------------------------------------------------
__device__ __forceinline__ void cpa16(void* s, const void* g) {
    uint32_t sa = (uint32_t)__cvta_generic_to_shared(s);
    asm volatile("cp.async.cg.shared.global [%0], [%1], 16;" :: "r"(sa), "l"(g));
}
__device__ __forceinline__ void ldsm4(uint32_t* r, const __nv_bfloat16* p) {
    uint32_t sa = (uint32_t)__cvta_generic_to_shared(p);
    asm volatile("ldmatrix.sync.aligned.m8n8.x4.shared.b16 {%0,%1,%2,%3}, [%4];"
                 : "=r"(r[0]), "=r"(r[1]), "=r"(r[2]), "=r"(r[3]) : "r"(sa));
}
__device__ __forceinline__ void mma16816(float* c, const uint32_t* a, const uint32_t* b) {
    asm volatile(
        "mma.sync.aligned.m16n8k16.row.col.f32.bf16.bf16.f32 "
        "{%0,%1,%2,%3}, {%4,%5,%6,%7}, {%8,%9}, {%0,%1,%2,%3};"
        : "+f"(c[0]), "+f"(c[1]), "+f"(c[2]), "+f"(c[3])
        : "r"(a[0]), "r"(a[1]), "r"(a[2]), "r"(a[3]), "r"(b[0]), "r"(b[1]));
}

__global__ __launch_bounds__(128, 2) void gemm_kernel() {
    __shared__ __align__(16) __nv_bfloat16 sA[2][128 * 40];
    __shared__ __align__(16) __nv_bfloat16 sB[2][128 * 40];
    const int mt = blockIdx.y, nt = blockIdx.x;
    const int tid = threadIdx.x;
    const int lane = tid & 31, warp = tid >> 5;
    const int wm = warp >> 1, wn = warp & 1;   // 2x2 warp grid, 64x64 each

    float acc[4][8][4];
#pragma unroll
    for (int a = 0; a < 4; a++)
#pragma unroll
        for (int b = 0; b < 8; b++)
#pragma unroll
            for (int c = 0; c < 4; c++) acc[a][b][c] = 0.f;

    // tile loader: each array 128 rows x 32 cols bf16 = 512 16B-chunks,
    // 128 threads -> 4 chunks per thread per array.
    auto load_tiles = [&](int buf, int k0) {
#pragma unroll
        for (int u = 0; u < 4; ++u) {
            int ch = tid + u * 128;
            int row = ch >> 2, c4 = ch & 3;
            cpa16(&sA[buf][row * 40 + c4 * 8],
                  g_Xt + (size_t)(mt * 128 + row) * CCH + k0 + c4 * 8);
            cpa16(&sB[buf][row * 40 + c4 * 8],
                  g_Yt + (size_t)(nt * 128 + row) * CCH + k0 + c4 * 8);
        }
        asm volatile("cp.async.commit_group;");
    };

    load_tiles(0, 0);
    const int NKI = CCH / 32;  // 8
    for (int kk = 0; kk < NKI; ++kk) {
        int buf = kk & 1;
        if (kk + 1 < NKI) {
            load_tiles(buf ^ 1, (kk + 1) * 32);
            asm volatile("cp.async.wait_group 1;");
        } else {
            asm volatile("cp.async.wait_group 0;");
        }
        __syncthreads();
#pragma unroll
        for (int ks = 0; ks < 2; ++ks) {
            // A fragments: 4 x ldsm4 (64 rows x k16)
            uint32_t afr[4][4];
#pragma unroll
            for (int mi = 0; mi < 4; ++mi) {
                int r = wm * 64 + mi * 16 + (lane & 7) + ((lane >> 3) & 1) * 8;
                int cch = ks * 2 + (lane >> 4);
                ldsm4(afr[mi], &sA[buf][r * 40 + cch * 8]);
            }
            // B fragments: 4 x ldsm4, each covers two n8 tiles x k16
            uint32_t bfr[8][2];
#pragma unroll
            for (int nip = 0; nip < 4; ++nip) {
                uint32_t q[4];
                int r = wn * 64 + nip * 16 + ((lane >> 4) & 1) * 8 + (lane & 7);
                int cch = ks * 2 + ((lane >> 3) & 1);
                ldsm4(q, &sB[buf][r * 40 + cch * 8]);
                bfr[nip * 2][0] = q[0];     bfr[nip * 2][1] = q[1];
                bfr[nip * 2 + 1][0] = q[2]; bfr[nip * 2 + 1][1] = q[3];
            }
#pragma unroll
            for (int mi = 0; mi < 4; ++mi)
#pragma unroll
                for (int ni = 0; ni < 8; ++ni)
                    mma16816(acc[mi][ni], afr[mi], bfr[ni]);
        }
        __syncthreads();
    }

    // Epilogue: convert to bf16 pairs and stream to g_Pb (coalesced 4B/lane)
#pragma unroll
    for (int mi = 0; mi < 4; ++mi) {
#pragma unroll
        for (int ni = 0; ni < 8; ++ni) {
            int r0 = mt * 128 + wm * 64 + mi * 16 + (lane >> 2);
            int c0 = nt * 128 + wn * 64 + ni * 8 + (lane & 3) * 2;
            __nv_bfloat162 v01 = __floats2bfloat162_rn(acc[mi][ni][0], acc[mi][ni][1]);
            __nv_bfloat162 v23 = __floats2bfloat162_rn(acc[mi][ni][2], acc[mi][ni][3]);
            *reinterpret_cast<__nv_bfloat162*>(&g_Pb[(size_t)r0 * NPIX + c0]) = v01;
            *reinterpret_cast<__nv_bfloat162*>(&g_Pb[(size_t)(r0 + 8) * NPIX + c0]) = v23;
        }
    }
}

// ---------------------------------------------------------------------------
// K2: fused 9-tap diagonal sum + invnorm scale + argmax on bf16 P.
// (round-9 version: base pointer + immediate tap offsets, FMAX tree)
// ---------------------------------------------------------------------------
__device__ __forceinline__ uint32_t badd2(uint32_t a, uint32_t b) {
    __nv_bfloat162 av, bv;
    *reinterpret_cast<uint32_t*>(&av) = a;
    *reinterpret_cast<uint32_t*>(&bv) = b;
    __nv_bfloat162 rv = __hadd2(av, bv);
    return *reinterpret_cast<uint32_t*>(&rv);
}

#define TAPOFF(t) (((t) / 3 * WW + (t) % 3) * NPIX + ((t) / 3 * WW))

__global__ __launch_bounds__(256) void argmax_kernel() {
    int w = threadIdx.x >> 5, lane = threadIdx.x & 31;
    int qid = blockIdx.x * 8 + w;
    if (qid >= QN) return;
    int i = qid / OHW, j = qid % OHW;
    const __nv_bfloat16* base = g_Pb + (size_t)(i * WW + j) * NPIX;

    float best = -3.0e38f;
    int bestY = 0;

#pragma unroll 1
    for (int g = 0; g < NPIX / 256; ++g) {   // 36 iterations
        const int off = g * 256 + lane * 8;
        const int ybase = off;
        const __nv_bfloat16* p = base + off;

        uint4 A0 = {0u, 0u, 0u, 0u}, A1 = A0, A2 = A0;
        uint32_t nA1 = 0u, nA2 = 0u;

#pragma unroll
        for (int t = 0; t < 9; ++t) {
            uint4 ch = __ldg(reinterpret_cast<const uint4*>(p + TAPOFF(t)));
            const int o = t % 3;
            if (o == 0) {
                A0.x = badd2(A0.x, ch.x); A0.y = badd2(A0.y, ch.y);
                A0.z = badd2(A0.z, ch.z); A0.w = badd2(A0.w, ch.w);
            } else if (o == 1) {
                A1.x = badd2(A1.x, ch.x); A1.y = badd2(A1.y, ch.y);
                A1.z = badd2(A1.z, ch.z); A1.w = badd2(A1.w, ch.w);
                if (lane == 31)
                    nA1 = badd2(nA1, __ldg(reinterpret_cast<const uint32_t*>(p + TAPOFF(t) + 8)));
            } else {
                A2.x = badd2(A2.x, ch.x); A2.y = badd2(A2.y, ch.y);
                A2.z = badd2(A2.z, ch.z); A2.w = badd2(A2.w, ch.w);
                if (lane == 31)
                    nA2 = badd2(nA2, __ldg(reinterpret_cast<const uint32_t*>(p + TAPOFF(t) + 8)));
            }
        }

        uint32_t n1 = __shfl_down_sync(0xFFFFFFFFu, A1.x, 1);
        uint32_t n2 = __shfl_down_sync(0xFFFFFFFFu, A2.x, 1);
        if (lane == 31) { n1 = nA1; n2 = nA2; }

        uint32_t b1[4], b2[4];
        b1[0] = __byte_perm(A1.x, A1.y, 0x5432);
        b1[1] = __byte_perm(A1.y, A1.z, 0x5432);
        b1[2] = __byte_perm(A1.z, A1.w, 0x5432);
        b1[3] = __byte_perm(A1.w, n1,   0x5432);
        b2[0] = A2.y; b2[1] = A2.z; b2[2] = A2.w; b2[3] = n2;

        float4 i0 = __ldg(reinterpret_cast<const float4*>(&g_invY[ybase]));
        float4 i1 = __ldg(reinterpret_cast<const float4*>(&g_invY[ybase + 4]));
        const float iv[8] = {i0.x, i0.y, i0.z, i0.w, i1.x, i1.y, i1.z, i1.w};
        const uint32_t a0w[4] = {A0.x, A0.y, A0.z, A0.w};
        float r[8];
#pragma unroll
        for (int wi = 0; wi < 4; ++wi) {
            float lo = __uint_as_float(a0w[wi] << 16) +
                       __uint_as_float(b1[wi] << 16) +
                       __uint_as_float(b2[wi] << 16);
            float hi = __uint_as_float(a0w[wi] & 0xFFFF0000u) +
                       __uint_as_float(b1[wi] & 0xFFFF0000u) +
                       __uint_as_float(b2[wi] & 0xFFFF0000u);
            r[wi * 2]     = lo * iv[wi * 2];
            r[wi * 2 + 1] = hi * iv[wi * 2 + 1];
        }

        float m01 = fmaxf(r[0], r[1]), m23 = fmaxf(r[2], r[3]);
        float m45 = fmaxf(r[4], r[5]), m67 = fmaxf(r[6], r[7]);
        float m = fmaxf(fmaxf(m01, m23), fmaxf(m45, m67));
        if (m > best) {
            best = m;
#pragma unroll
            for (int e = 7; e >= 0; --e)
                if (r[e] == m) bestY = ybase + e;
        }
    }

#pragma unroll
    for (int offw = 16; offw; offw >>= 1) {
        float ob = __shfl_xor_sync(0xFFFFFFFFu, best, offw);
        int oy = __shfl_xor_sync(0xFFFFFFFFu, bestY, offw);
        if (ob > best || (ob == best && oy < bestY)) { best = ob; bestY = oy; }
    }
    if (lane == 0)
        g_nn[qid] = (bestY / WW) * OHW + (bestY % WW);
}

// ---------------------------------------------------------------------------
// K3: exact fp32 gathered MSE from the raw images.
// ---------------------------------------------------------------------------
__global__ void loss_kernel(const float* __restrict__ inp, const float* __restrict__ tgt) {
    int q = blockIdx.x;       // < QN
    int tid = threadIdx.x;    // 256
    int snn = g_nn[q];
    int i = q / OHW, j = q % OHW;
    int u = snn / OHW, v = snn % OHW;
    float sum = 0.f;
#pragma unroll
    for (int it = 0; it < 9; ++it) {
        int d = it * 256 + tid;
        int c = d / 9, t = d - c * 9;
        int oa = c * (HH * WW) + (i + t / 3) * WW + (j + t % 3);
        int ob = c * (HH * WW) + (u + t / 3) * WW + (v + t % 3);
        float df = inp[oa] - tgt[ob];
        sum += df * df;
    }
    __shared__ float red[256];
    red[tid] = sum;
    __syncthreads();
    for (int s = 128; s > 0; s >>= 1) {
        if (tid < s) red[tid] += red[tid + s];
        __syncthreads();
    }
    if (tid == 0) g_loss[q] = red[0];
}

// K4: deterministic scalar reduce -> loss = sum / (QN * 2304)
__global__ void final_kernel(float* __restrict__ out) {
    __shared__ float red[1024];
    int tid = threadIdx.x;
    float acc = 0.f;
    for (int i = tid; i < QN; i += 1024) acc += g_loss[i];
    red[tid] = acc;
    __syncthreads();
    for (int s = 512; s > 0; s >>= 1) {
        if (tid < s) red[tid] += red[tid + s];
        __syncthreads();
    }
    if (tid == 0) out[0] = red[0] / ((float)QN * 2304.0f);
}

extern "C" void kernel_launch(void* const* d_in, const int* in_sizes, int n_in,
                              void* d_out, int out_size) {
    const float* inp = (const float*)d_in[0];   // input
    const float* tgt = (const float*)d_in[1];   // target
    float* out = (float*)d_out;

    dim3 tg(NPIX / 32, CCH / 32, 2);
    transpose_kernel<<<tg, 256>>>(inp, tgt);
    invnorm_kernel<<<QN, 256>>>();
    dim3 gg(MTIL, MTIL);
    gemm_kernel<<<gg, 128>>>();
    argmax_kernel<<<(QN + 7) / 8, 256>>>();
    loss_kernel<<<QN, 256>>>(inp, tgt);
    final_kernel<<<1, 1024>>>(out);
}

// round 13
// speedup vs baseline: 1.7984x; 1.0918x over previous
#include <cuda_runtime.h>
#include <cuda_bf16.h>
#include <cstdint>

// Problem constants
#define HH 96
#define WW 96
#define NPIX 9216          // 96*96
#define OHW 94
#define QN 8836            // 94*94 patches on each side
#define CCH 256            // channels = GEMM K
#define MTIL 72            // 9216 / 128

// Static device scratch (no runtime allocation)
__device__ __nv_bfloat16 g_Xt[(size_t)NPIX * CCH];     // inp transposed  [pix][c] bf16
__device__ __nv_bfloat16 g_Yt[(size_t)NPIX * CCH];     // tgt transposed  [pix][c] bf16
// +4*NPIX zero pad: tail tap rows (x0+197) + column overreads stay in-bounds;
// device globals are zero-initialized, so pad reads are 0.0.
__device__ __nv_bfloat16 g_Pb[(size_t)NPIX * NPIX + 4 * NPIX];
__device__ float g_invY[NPIX];                         // 1/style_norm by y (0 if invalid)
__device__ int   g_nn[QN];
__device__ float g_loss[QN];

// ---------------------------------------------------------------------------
// K0: transpose+convert images: [256][9216] fp32 -> [9216][256] bf16
// ---------------------------------------------------------------------------
__global__ void transpose_kernel(const float* __restrict__ inp, const float* __restrict__ tgt) {
    __shared__ float t[32][33];
    const float* src = blockIdx.z ? tgt : inp;
    __nv_bfloat16* dst = blockIdx.z ? g_Yt : g_Xt;
    int p0 = blockIdx.x * 32, c0 = blockIdx.y * 32;
    int tx = threadIdx.x & 31, ty = threadIdx.x >> 5;  // 32 x 8
#pragma unroll
    for (int r = 0; r < 4; ++r) {
        int c = c0 + ty + r * 8;
        t[ty + r * 8][tx] = src[(size_t)c * NPIX + p0 + tx];
    }
    __syncthreads();
#pragma unroll
    for (int r = 0; r < 4; ++r) {
        int p = p0 + ty + r * 8;
        dst[(size_t)p * CCH + c0 + tx] = __float2bfloat16(t[tx][ty + r * 8]);
    }
}

// ---------------------------------------------------------------------------
// K0b: style patch inverse norms -> g_invY[y], y = u*96+v (0 elsewhere;
// zero-init at module load, invalid slots never written)
// ---------------------------------------------------------------------------
__global__ void invnorm_kernel() {
    int q = blockIdx.x;            // 0..QN-1
    int tid = threadIdx.x;         // 256 = one channel each
    int u = q / OHW, v = q % OHW;
    int y = u * WW + v;
    float ss = 0.f;
#pragma unroll
    for (int t = 0; t < 9; ++t) {
        int pix = y + (t / 3) * WW + (t % 3);
        float val = __bfloat162float(g_Yt[(size_t)pix * CCH + tid]);
        ss += val * val;
    }
    __shared__ float red[256];
    red[tid] = ss;
    __syncthreads();
    for (int s = 128; s > 0; s >>= 1) {
        if (tid < s) red[tid] += red[tid + s];
        __syncthreads();
    }
    if (tid == 0) g_invY[y] = 1.0f / sqrtf(red[0]);
}

// ---------------------------------------------------------------------------
// K1: P = Xt * Yt^T (9216x9216x256 bf16 -> bf16). 128x128 CTA tile, 4 warps,
// warp tile 64x64, double-buffered cp.async. (round-10/11 validated, unchanged)
// ---------------------------------------------------------------------------
__device__ __forceinline__ void cpa16(void* s, const void* g) {
    uint32_t sa = (uint32_t)__cvta_generic_to_shared(s);
    asm volatile("cp.async.cg.shared.global [%0], [%1], 16;" :: "r"(sa), "l"(g));
}
__device__ __forceinline__ void ldsm4(uint32_t* r, const __nv_bfloat16* p) {
    uint32_t sa = (uint32_t)__cvta_generic_to_shared(p);
    asm volatile("ldmatrix.sync.aligned.m8n8.x4.shared.b16 {%0,%1,%2,%3}, [%4];"
                 : "=r"(r[0]), "=r"(r[1]), "=r"(r[2]), "=r"(r[3]) : "r"(sa));
}
__device__ __forceinline__ void mma16816(float* c, const uint32_t* a, const uint32_t* b) {
    asm volatile(
        "mma.sync.aligned.m16n8k16.row.col.f32.bf16.bf16.f32 "
        "{%0,%1,%2,%3}, {%4,%5,%6,%7}, {%8,%9}, {%0,%1,%2,%3};"
        : "+f"(c[0]), "+f"(c[1]), "+f"(c[2]), "+f"(c[3])
        : "r"(a[0]), "r"(a[1]), "r"(a[2]), "r"(a[3]), "r"(b[0]), "r"(b[1]));
}

__global__ __launch_bounds__(128, 2) void gemm_kernel() {
    __shared__ __align__(16) __nv_bfloat16 sA[2][128 * 40];
    __shared__ __align__(16) __nv_bfloat16 sB[2][128 * 40];
    const int mt = blockIdx.y, nt = blockIdx.x;
    const int tid = threadIdx.x;
    const int lane = tid & 31, warp = tid >> 5;
    const int wm = warp >> 1, wn = warp & 1;   // 2x2 warp grid, 64x64 each

    float acc[4][8][4];
#pragma unroll
    for (int a = 0; a < 4; a++)
#pragma unroll
        for (int b = 0; b < 8; b++)
#pragma unroll
            for (int c = 0; c < 4; c++) acc[a][b][c] = 0.f;

    auto load_tiles = [&](int buf, int k0) {
#pragma unroll
        for (int u = 0; u < 4; ++u) {
            int ch = tid + u * 128;
            int row = ch >> 2, c4 = ch & 3;
            cpa16(&sA[buf][row * 40 + c4 * 8],
                  g_Xt + (size_t)(mt * 128 + row) * CCH + k0 + c4 * 8);
            cpa16(&sB[buf][row * 40 + c4 * 8],
                  g_Yt + (size_t)(nt * 128 + row) * CCH + k0 + c4 * 8);
        }
        asm volatile("cp.async.commit_group;");
    };

    load_tiles(0, 0);
    const int NKI = CCH / 32;  // 8
    for (int kk = 0; kk < NKI; ++kk) {
        int buf = kk & 1;
        if (kk + 1 < NKI) {
            load_tiles(buf ^ 1, (kk + 1) * 32);
            asm volatile("cp.async.wait_group 1;");
        } else {
            asm volatile("cp.async.wait_group 0;");
        }
        __syncthreads();
#pragma unroll
        for (int ks = 0; ks < 2; ++ks) {
            uint32_t afr[4][4];
#pragma unroll
            for (int mi = 0; mi < 4; ++mi) {
                int r = wm * 64 + mi * 16 + (lane & 7) + ((lane >> 3) & 1) * 8;
                int cch = ks * 2 + (lane >> 4);
                ldsm4(afr[mi], &sA[buf][r * 40 + cch * 8]);
            }
            uint32_t bfr[8][2];
#pragma unroll
            for (int nip = 0; nip < 4; ++nip) {
                uint32_t q[4];
                int r = wn * 64 + nip * 16 + ((lane >> 4) & 1) * 8 + (lane & 7);
                int cch = ks * 2 + ((lane >> 3) & 1);
                ldsm4(q, &sB[buf][r * 40 + cch * 8]);
                bfr[nip * 2][0] = q[0];     bfr[nip * 2][1] = q[1];
                bfr[nip * 2 + 1][0] = q[2]; bfr[nip * 2 + 1][1] = q[3];
            }
#pragma unroll
            for (int mi = 0; mi < 4; ++mi)
#pragma unroll
                for (int ni = 0; ni < 8; ++ni)
                    mma16816(acc[mi][ni], afr[mi], bfr[ni]);
        }
        __syncthreads();
    }

#pragma unroll
    for (int mi = 0; mi < 4; ++mi) {
#pragma unroll
        for (int ni = 0; ni < 8; ++ni) {
            int r0 = mt * 128 + wm * 64 + mi * 16 + (lane >> 2);
            int c0 = nt * 128 + wn * 64 + ni * 8 + (lane & 3) * 2;
            __nv_bfloat162 v01 = __floats2bfloat162_rn(acc[mi][ni][0], acc[mi][ni][1]);
            __nv_bfloat162 v23 = __floats2bfloat162_rn(acc[mi][ni][2], acc[mi][ni][3]);
            *reinterpret_cast<__nv_bfloat162*>(&g_Pb[(size_t)r0 * NPIX + c0]) = v01;
            *reinterpret_cast<__nv_bfloat162*>(&g_Pb[(size_t)(r0 + 8) * NPIX + c0]) = v23;
        }
    }
}

// ---------------------------------------------------------------------------
// K2: fused 9-tap diagonal sum + invnorm scale + argmax on bf16 P.
// One warp handles 4 consecutive q (same i, j0..j0+3). Shared row-sums:
//   S[k][e] = sum_dh P[x0 + dh*96 + k][dh*96 + off + e]      (k = 0..5)
// (FIX vs failed R12: column base includes + dh*96, matching the diagonal
// structure resp[y] = sum P[x+dl][y+dl].)
// For q=jo: realign S[jo+dw] by dw elements -> column y + dh*96 + dw. 18 LDG
// per warp-iter serves 4 q's (was 36); invY loads shared 4-way.
// ---------------------------------------------------------------------------
__device__ __forceinline__ uint32_t badd2(uint32_t a, uint32_t b) {
    __nv_bfloat162 av, bv;
    *reinterpret_cast<uint32_t*>(&av) = a;
    *reinterpret_cast<uint32_t*>(&bv) = b;
    __nv_bfloat162 rv = __hadd2(av, bv);
    return *reinterpret_cast<uint32_t*>(&rv);
}

#define NJG 24   // j-groups of 4 per image row (24*4 = 96 >= 94)

__global__ __launch_bounds__(256) void argmax_kernel() {
    const int w = threadIdx.x >> 5, lane = threadIdx.x & 31;
    const int task = blockIdx.x * 8 + w;        // 0 .. 94*24-1 (exact)
    const int i = task / NJG, jg = task % NJG;
    const int j0 = jg * 4;
    const __nv_bfloat16* base = g_Pb + (size_t)(i * WW + j0) * NPIX;

    float best[4];
    int bY[4];
#pragma unroll
    for (int jo = 0; jo < 4; ++jo) { best[jo] = -3.0e38f; bY[jo] = 0; }

#pragma unroll 1
    for (int g = 0; g < NPIX / 256; ++g) {   // 36 iterations
        const int off = g * 256 + lane * 8;  // ybase for this lane
        const __nv_bfloat16* p = base + off;

        uint32_t S[6][4];
        uint32_t nS[6];                      // lane-31 boundary words (k>=1)
#pragma unroll
        for (int k = 0; k < 6; ++k) {
            S[k][0] = S[k][1] = S[k][2] = S[k][3] = 0u;
            nS[k] = 0u;
        }
#pragma unroll
        for (int dh = 0; dh < 3; ++dh) {
#pragma unroll
            for (int k = 0; k < 6; ++k) {
                // row shift (dh*96 + k) AND column shift dh*96 (diagonal!)
                const int ro = (dh * WW + k) * NPIX + dh * WW;   // compile-time
                uint4 ch = __ldg(reinterpret_cast<const uint4*>(p + ro));
                S[k][0] = badd2(S[k][0], ch.x);
                S[k][1] = badd2(S[k][1], ch.y);
                S[k][2] = badd2(S[k][2], ch.z);
                S[k][3] = badd2(S[k][3], ch.w);
                if (k >= 1 && lane == 31)
                    nS[k] = badd2(nS[k], __ldg(reinterpret_cast<const uint32_t*>(p + ro + 8)));
            }
        }

        // Boundary words: next lane's first word of S[k] (elements 8,9).
        uint32_t nb[6];
#pragma unroll
        for (int k = 1; k < 6; ++k) {
            nb[k] = __shfl_down_sync(0xFFFFFFFFu, S[k][0], 1);
            if (lane == 31) nb[k] = nS[k];
        }

        // invY strip, shared by all 4 q's.
        float4 i0 = __ldg(reinterpret_cast<const float4*>(&g_invY[off]));
        float4 i1 = __ldg(reinterpret_cast<const float4*>(&g_invY[off + 4]));
        const float iv[8] = {i0.x, i0.y, i0.z, i0.w, i1.x, i1.y, i1.z, i1.w};

#pragma unroll
        for (int jo = 0; jo < 4; ++jo) {
            // A0 = S[jo] (shift 0), A1 = S[jo+1] (shift 1), A2 = S[jo+2] (shift 2)
            uint32_t b1[4], b2[4];
            b1[0] = __byte_perm(S[jo + 1][0], S[jo + 1][1], 0x5432);
            b1[1] = __byte_perm(S[jo + 1][1], S[jo + 1][2], 0x5432);
            b1[2] = __byte_perm(S[jo + 1][2], S[jo + 1][3], 0x5432);
            b1[3] = __byte_perm(S[jo + 1][3], nb[jo + 1],   0x5432);
            b2[0] = S[jo + 2][1]; b2[1] = S[jo + 2][2];
            b2[2] = S[jo + 2][3]; b2[3] = nb[jo + 2];

            float r[8];
#pragma unroll
            for (int wi = 0; wi < 4; ++wi) {
                float lo = __uint_as_float(S[jo][wi] << 16) +
                           __uint_as_float(b1[wi] << 16) +
                           __uint_as_float(b2[wi] << 16);
                float hi = __uint_as_float(S[jo][wi] & 0xFFFF0000u) +
                           __uint_as_float(b1[wi] & 0xFFFF0000u) +
                           __uint_as_float(b2[wi] & 0xFFFF0000u);
                r[wi * 2]     = lo * iv[wi * 2];
                r[wi * 2 + 1] = hi * iv[wi * 2 + 1];
            }

            float m01 = fmaxf(r[0], r[1]), m23 = fmaxf(r[2], r[3]);
            float m45 = fmaxf(r[4], r[5]), m67 = fmaxf(r[6], r[7]);
            float m = fmaxf(fmaxf(m01, m23), fmaxf(m45, m67));
            if (m > best[jo]) {
                best[jo] = m;
#pragma unroll
                for (int e = 7; e >= 0; --e)
                    if (r[e] == m) bY[jo] = off + e;
            }
        }
    }

    // Per-q warp reduce: largest resp, tie -> smallest y (jnp.argmax).
#pragma unroll
    for (int jo = 0; jo < 4; ++jo) {
        float b = best[jo];
        int y = bY[jo];
#pragma unroll
        for (int offw = 16; offw; offw >>= 1) {
            float ob = __shfl_xor_sync(0xFFFFFFFFu, b, offw);
            int oy = __shfl_xor_sync(0xFFFFFFFFu, y, offw);
            if (ob > b || (ob == b && oy < y)) { b = ob; y = oy; }
        }
        int j = j0 + jo;
        if (lane == 0 && j < OHW)
            g_nn[i * OHW + j] = (y / WW) * OHW + (y % WW);
    }
}

// ---------------------------------------------------------------------------
// K3: exact fp32 gathered MSE from the raw images.
// ---------------------------------------------------------------------------
__global__ void loss_kernel(const float* __restrict__ inp, const float* __restrict__ tgt) {
    int q = blockIdx.x;       // < QN
    int tid = threadIdx.x;    // 256
    int snn = g_nn[q];
    int i = q / OHW, j = q % OHW;
    int u = snn / OHW, v = snn % OHW;
    float sum = 0.f;
#pragma unroll
    for (int it = 0; it < 9; ++it) {
        int d = it * 256 + tid;
        int c = d / 9, t = d - c * 9;
        int oa = c * (HH * WW) + (i + t / 3) * WW + (j + t % 3);
        int ob = c * (HH * WW) + (u + t / 3) * WW + (v + t % 3);
        float df = inp[oa] - tgt[ob];
        sum += df * df;
    }
    __shared__ float red[256];
    red[tid] = sum;
    __syncthreads();
    for (int s = 128; s > 0; s >>= 1) {
        if (tid < s) red[tid] += red[tid + s];
        __syncthreads();
    }
    if (tid == 0) g_loss[q] = red[0];
}

// K4: deterministic scalar reduce -> loss = sum / (QN * 2304)
__global__ void final_kernel(float* __restrict__ out) {
    __shared__ float red[1024];
    int tid = threadIdx.x;
    float acc = 0.f;
    for (int i = tid; i < QN; i += 1024) acc += g_loss[i];
    red[tid] = acc;
    __syncthreads();
    for (int s = 512; s > 0; s >>= 1) {
        if (tid < s) red[tid] += red[tid + s];
        __syncthreads();
    }
    if (tid == 0) out[0] = red[0] / ((float)QN * 2304.0f);
}

extern "C" void kernel_launch(void* const* d_in, const int* in_sizes, int n_in,
                              void* d_out, int out_size) {
    const float* inp = (const float*)d_in[0];   // input
    const float* tgt = (const float*)d_in[1];   // target
    float* out = (float*)d_out;

    dim3 tg(NPIX / 32, CCH / 32, 2);
    transpose_kernel<<<tg, 256>>>(inp, tgt);
    invnorm_kernel<<<QN, 256>>>();
    dim3 gg(MTIL, MTIL);
    gemm_kernel<<<gg, 128>>>();
    argmax_kernel<<<(OHW * NJG) / 8, 256>>>();
    loss_kernel<<<QN, 256>>>(inp, tgt);
    final_kernel<<<1, 1024>>>(out);
}